// round 5
// baseline (speedup 1.0000x reference)
#include <cuda_runtime.h>
#include <math.h>

#define VOL (128*128*128)

// Accumulators (double): 0 reg_sumsq | 1-3 pair0 cross/gg/pp | 4-6 pair1 | 7-8 tv0 prod/sum | 9-10 tv1
// Zero at load; the last-finishing block reads them, emits the result, and
// re-zeroes them so every graph replay starts from the same state.
__device__ double g_acc[12];
__device__ unsigned g_ticket;

__device__ __forceinline__ float warp_sum(float v) {
    #pragma unroll
    for (int o = 16; o > 0; o >>= 1) v += __shfl_xor_sync(0xffffffffu, v, o);
    return v;
}

// ---------------------------------------------------------------------------
// Fused kernel. Roles interleaved: blk%7 in {0..3} lcc | {4,5} reg | {6} tversky
// so every scheduling wave mixes compute-bound and memory-bound blocks.
// ---------------------------------------------------------------------------
#define TX 32
#define TY 8
#define TZ 32
#define HX 36
#define HY 12
#define NSLICE (TZ + 4)
#define SLICE_ELEMS (HY * HX)   // 432
#define XS_ELEMS (HY * TX)      // 384

#define TOTAL_BLOCKS 1792       // 256 groups of 7
#define REG_BLOCKS 512
#define TV_BLOCKS  256

__global__ __launch_bounds__(256) void fused_kernel(
    const float* __restrict__ F0, const float* __restrict__ F0g,
    const float* __restrict__ I0, const float* __restrict__ I0R,
    const float* __restrict__ I1, const float* __restrict__ I1R,
    const float* __restrict__ S0, const float* __restrict__ S0g,
    const float* __restrict__ S1, const float* __restrict__ S1g,
    float* __restrict__ out) {

    __shared__ float2 raw[2][SLICE_ELEMS];
    __shared__ float2 xs[2][XS_ELEMS];

    int grp = blockIdx.x / 7;     // 0..255
    int role = blockIdx.x % 7;    // 0-3 lcc, 4-5 reg, 6 tv
    int tid = threadIdx.x;

    if (role < 4) {
        // ================= LCC: pipelined z-march =================
        int blk = grp * 4 + role;   // 0..1023
        int x0 = (blk & 3) * TX;
        int y0 = ((blk >> 2) & 15) * TY;
        int z0 = ((blk >> 6) & 3) * TZ;
        int batch = (blk >> 8) & 1;
        int pair = blk >> 9;

        const float* gt = (pair == 0 ? I0 : I1) + (size_t)batch * VOL;
        const float* pr = (pair == 0 ? I0R : I1R) + (size_t)batch * VOL;

        int lx = tid & 31, ly = tid >> 5;

        int e0 = tid, e1 = tid + 256;
        int l0y = e0 / HX, l0x = e0 - l0y * HX;
        int l1y = e1 / HX, l1x = e1 - l1y * HX;
        int gx0 = x0 + l0x - 2, gy0 = y0 + l0y - 2;
        int gx1 = x0 + l1x - 2, gy1 = y0 + l1y - 2;
        bool hasE1 = (e1 < SLICE_ELEMS);  // tid < 176
        bool v0 = ((unsigned)gx0 < 128u) & ((unsigned)gy0 < 128u);
        bool v1 = hasE1 & ((unsigned)gx1 < 128u) & ((unsigned)gy1 < 128u);
        int zbase = z0 - 2;
        size_t zb = (size_t)zbase * (128 * 128);
        const float* pg0 = gt + (v0 ? (gy0 * 128 + gx0) : 0) + zb;
        const float* pp0 = pr + (v0 ? (gy0 * 128 + gx0) : 0) + zb;
        const float* pg1 = gt + (v1 ? (gy1 * 128 + gx1) : 0) + zb;
        const float* pp1 = pr + (v1 ? (gy1 * 128 + gx1) : 0) + zb;

        bool hasF1 = (tid < XS_ELEMS - 256);  // tid < 128

        // prologue: slice 0
        {
            bool zv = (unsigned)(zbase) < 128u;
            float a = 0.f, b = 0.f, c = 0.f, d = 0.f;
            if (v0 & zv) { a = pg0[0]; b = pp0[0]; }
            if (v1 & zv) { c = pg1[0]; d = pp1[0]; }
            raw[0][e0] = make_float2(a, b);
            if (hasE1) raw[0][e1] = make_float2(c, d);
        }
        __syncthreads();

        float2 bgp[5], cgp[5];
        #pragma unroll
        for (int k = 0; k < 5; k++) { bgp[k] = make_float2(0.f, 0.f); cgp[k] = make_float2(0.f, 0.f); }
        float accC = 0.f, accG = 0.f, accP = 0.f;

        #pragma unroll
        for (int zi = 0; zi < NSLICE; zi++) {
            const int cur = zi & 1, nxt = cur ^ 1;

            // prefetch slice zi+1 into registers (overlaps x-pass)
            float ng0 = 0.f, np0 = 0.f, ng1 = 0.f, np1 = 0.f;
            if (zi + 1 < NSLICE) {
                bool zv = (unsigned)(zbase + zi + 1) < 128u;
                const int zo = (zi + 1) * (128 * 128);
                if (v0 & zv) { ng0 = pg0[zo]; np0 = pp0[zo]; }
                if (v1 & zv) { ng1 = pg1[zo]; np1 = pp1[zo]; }
            }

            // x-pass: 5-wide from raw[cur] into xs[cur]; capture center
            {
                const float2* r = &raw[cur][ly * HX + lx];
                float2 s;
                s.x = r[0].x + r[1].x + r[2].x + r[3].x + r[4].x;
                s.y = r[0].y + r[1].y + r[2].y + r[3].y + r[4].y;
                xs[cur][tid] = s;
                if (hasF1) {
                    const float2* r2 = &raw[cur][(8 + ly) * HX + lx];
                    float2 s2;
                    s2.x = r2[0].x + r2[1].x + r2[2].x + r2[3].x + r2[4].x;
                    s2.y = r2[0].y + r2[1].y + r2[2].y + r2[3].y + r2[4].y;
                    xs[cur][tid + 256] = s2;
                }
                cgp[zi % 5] = raw[cur][(ly + 2) * HX + lx + 2];
            }

            // stage prefetched slice into raw[nxt]
            raw[nxt][e0] = make_float2(ng0, np0);
            if (hasE1) raw[nxt][e1] = make_float2(ng1, np1);
            __syncthreads();

            // y-pass from xs[cur]; z-pass in register ring
            {
                const float2* q = &xs[cur][ly * TX + lx];
                float2 w;
                w.x = q[0].x + q[TX].x + q[2 * TX].x + q[3 * TX].x + q[4 * TX].x;
                w.y = q[0].y + q[TX].y + q[2 * TX].y + q[3 * TX].y + q[4 * TX].y;
                bgp[zi % 5] = w;
            }

            if (zi >= 4) {
                float sg = bgp[0].x + bgp[1].x + bgp[2].x + bgp[3].x + bgp[4].x;
                float sp = bgp[0].y + bgp[1].y + bgp[2].y + bgp[3].y + bgp[4].y;
                float2 c = cgp[(zi - 2) % 5];
                float dgv = c.x - sg * (1.f / 125.f);
                float dpv = c.y - sp * (1.f / 125.f);
                accG += dgv * dgv;
                accP += dpv * dpv;
                accC += dgv * dpv;
            }
        }

        float* scr = (float*)&xs[0][0];
        float c = warp_sum(accC);
        float gg = warp_sum(accG);
        float pp = warp_sum(accP);
        int wid = tid >> 5, lane = tid & 31;
        __syncthreads();
        if (lane == 0) { scr[wid] = c; scr[8 + wid] = gg; scr[16 + wid] = pp; }
        __syncthreads();
        if (tid == 0) {
            float C = 0, G = 0, P = 0;
            #pragma unroll
            for (int w = 0; w < 8; w++) { C += scr[w]; G += scr[8 + w]; P += scr[16 + w]; }
            int base = 1 + pair * 3;
            atomicAdd(&g_acc[base + 0], (double)C);
            atomicAdd(&g_acc[base + 1], (double)G);
            atomicAdd(&g_acc[base + 2], (double)P);
        }
    } else if (role < 6) {
        // ================= reg_field: sum((a-b)^2) =================
        const float4* a = (const float4*)F0;
        const float4* b = (const float4*)F0g;
        const int n4 = (2 * 3 * VOL) / 4;
        int bid = grp * 2 + (role - 4);   // 0..511
        float acc = 0.f;
        for (int i = bid * 256 + tid; i < n4; i += REG_BLOCKS * 256) {
            float4 x = a[i], y = b[i];
            float d0 = x.x - y.x, d1 = x.y - y.y, d2 = x.z - y.z, d3 = x.w - y.w;
            acc += d0 * d0 + d1 * d1 + d2 * d2 + d3 * d3;
        }
        float* scr = (float*)&xs[0][0];
        float w = warp_sum(acc);
        if ((tid & 31) == 0) scr[tid >> 5] = w;
        __syncthreads();
        if (tid == 0) {
            float v = 0.f;
            #pragma unroll
            for (int k = 0; k < 8; k++) v += scr[k];
            atomicAdd(&g_acc[0], (double)v);
        }
    } else {
        // ================= tversky: both pairs =================
        const float4* g0 = (const float4*)S0;
        const float4* p0 = (const float4*)S0g;
        const float4* g1 = (const float4*)S1;
        const float4* p1 = (const float4*)S1g;
        const int n4 = (2 * VOL) / 4;
        int bid = grp;   // 0..255
        float pr0 = 0.f, sm0 = 0.f, pr1 = 0.f, sm1 = 0.f;
        for (int i = bid * 256 + tid; i < n4; i += TV_BLOCKS * 256) {
            float4 a = g0[i], b = p0[i];
            pr0 += a.x * b.x + a.y * b.y + a.z * b.z + a.w * b.w;
            sm0 += a.x + b.x + a.y + b.y + a.z + b.z + a.w + b.w;
            float4 cc = g1[i], dd = p1[i];
            pr1 += cc.x * dd.x + cc.y * dd.y + cc.z * dd.z + cc.w * dd.w;
            sm1 += cc.x + dd.x + cc.y + dd.y + cc.z + dd.z + cc.w + dd.w;
        }
        float* scr = (float*)&xs[0][0];
        float v0 = warp_sum(pr0), v1 = warp_sum(sm0), v2 = warp_sum(pr1), v3 = warp_sum(sm1);
        int wid = tid >> 5;
        if ((tid & 31) == 0) { scr[wid] = v0; scr[8 + wid] = v1; scr[16 + wid] = v2; scr[24 + wid] = v3; }
        __syncthreads();
        if (tid == 0) {
            float t0 = 0, t1 = 0, t2 = 0, t3 = 0;
            #pragma unroll
            for (int k = 0; k < 8; k++) { t0 += scr[k]; t1 += scr[8 + k]; t2 += scr[16 + k]; t3 += scr[24 + k]; }
            atomicAdd(&g_acc[7], (double)t0);
            atomicAdd(&g_acc[8], (double)t1);
            atomicAdd(&g_acc[9], (double)t2);
            atomicAdd(&g_acc[10], (double)t3);
        }
    }

    // ---- last-block-done finalize (thread 0 of each block takes a ticket) ----
    if (tid == 0) {
        __threadfence();
        unsigned t = atomicAdd(&g_ticket, 1u);
        if (t == TOTAL_BLOCKS - 1) {
            __threadfence();
            volatile double* acc = g_acc;

            const double omega_f = 2.0 * 3.0 * VOL;  // 12582912
            const double omega_i = 2.0 * 1.0 * VOL;  // 4194304

            double rf = sqrt(acc[0]) / omega_f;

            double num0 = acc[1] * acc[1];
            double den0 = acc[2] * acc[3];
            den0 = den0 > 1e-5 ? den0 : 1e-5;
            double lcc0 = -(num0 / den0) / omega_i;

            double num1 = acc[4] * acc[4];
            double den1 = acc[5] * acc[6];
            den1 = den1 > 1e-5 ? den1 : 1e-5;
            double lcc1 = -(num1 / den1) / omega_i;

            double s0 = acc[8] > 1e-5 ? acc[8] : 1e-5;
            double s1 = acc[10] > 1e-5 ? acc[10] : 1e-5;
            double tv0 = -acc[7] / s0;   // -0.5 * 2*prod / sum
            double tv1 = -acc[9] / s1;

            out[0] = (float)(rf + 10.0 * (lcc0 + lcc1) + 10.0 * (tv0 + tv1));

            // reset state for the next replay
            #pragma unroll
            for (int k = 0; k < 12; k++) g_acc[k] = 0.0;
            __threadfence();
            g_ticket = 0u;
        }
    }
}

extern "C" void kernel_launch(void* const* d_in, const int* in_sizes, int n_in,
                              void* d_out, int out_size) {
    const float* F0  = (const float*)d_in[0];
    const float* F0g = (const float*)d_in[1];
    const float* I0  = (const float*)d_in[2];
    const float* I0R = (const float*)d_in[3];
    const float* I1  = (const float*)d_in[4];
    const float* I1R = (const float*)d_in[5];
    const float* S0  = (const float*)d_in[6];
    const float* S0g = (const float*)d_in[7];
    const float* S1  = (const float*)d_in[8];
    const float* S1g = (const float*)d_in[9];
    float* out = (float*)d_out;

    fused_kernel<<<TOTAL_BLOCKS, 256>>>(F0, F0g, I0, I0R, I1, I1R,
                                        S0, S0g, S1, S1g, out);
}

// round 6
// speedup vs baseline: 1.0870x; 1.0870x over previous
#include <cuda_runtime.h>
#include <math.h>

#define VOL (128*128*128)

// Accumulators (double): 0 reg_sumsq | 1-3 pair0 cross/gg/pp | 4-6 pair1 | 7-8 tv0 prod/sum | 9-10 tv1
// Zero at load; the last-finishing block reads them, emits the result, and
// re-zeroes them so every graph replay starts from the same state.
__device__ double g_acc[12];
__device__ unsigned g_ticket;

__device__ __forceinline__ float warp_sum(float v) {
    #pragma unroll
    for (int o = 16; o > 0; o >>= 1) v += __shfl_xor_sync(0xffffffffu, v, o);
    return v;
}

// ---------------------------------------------------------------------------
// Fused kernel, segregated roles: blocks [0,1024) lcc | [1024,1536) reg |
// [1536,1792) tversky. Scheduler backfills streaming blocks as lcc drains.
// ---------------------------------------------------------------------------
#define TX 32
#define TY 8
#define TZ 32
#define HX 36
#define HY 12
#define NSLICE (TZ + 4)
#define SLICE_ELEMS (HY * HX)   // 432
#define XS_ELEMS (HY * TX)      // 384

#define LCC_BLOCKS 1024
#define REG_BLOCKS 512
#define TV_BLOCKS  256
#define TOTAL_BLOCKS (LCC_BLOCKS + REG_BLOCKS + TV_BLOCKS)

__global__ __launch_bounds__(256, 5) void fused_kernel(
    const float* __restrict__ F0, const float* __restrict__ F0g,
    const float* __restrict__ I0, const float* __restrict__ I0R,
    const float* __restrict__ I1, const float* __restrict__ I1R,
    const float* __restrict__ S0, const float* __restrict__ S0g,
    const float* __restrict__ S1, const float* __restrict__ S1g,
    float* __restrict__ out) {

    __shared__ float2 raw[2][SLICE_ELEMS];
    __shared__ float2 xs[2][XS_ELEMS];

    int blkid = blockIdx.x;
    int tid = threadIdx.x;

    if (blkid < LCC_BLOCKS) {
        // ================= LCC: pipelined z-march =================
        int blk = blkid;
        int x0 = (blk & 3) * TX;
        int y0 = ((blk >> 2) & 15) * TY;
        int z0 = ((blk >> 6) & 3) * TZ;
        int batch = (blk >> 8) & 1;
        int pair = blk >> 9;

        const float* gt = (pair == 0 ? I0 : I1) + (size_t)batch * VOL;
        const float* pr = (pair == 0 ? I0R : I1R) + (size_t)batch * VOL;

        int lx = tid & 31, ly = tid >> 5;

        int e0 = tid, e1 = tid + 256;
        int l0y = e0 / HX, l0x = e0 - l0y * HX;
        int l1y = e1 / HX, l1x = e1 - l1y * HX;
        int gx0 = x0 + l0x - 2, gy0 = y0 + l0y - 2;
        int gx1 = x0 + l1x - 2, gy1 = y0 + l1y - 2;
        bool hasE1 = (e1 < SLICE_ELEMS);  // tid < 176
        bool v0 = ((unsigned)gx0 < 128u) & ((unsigned)gy0 < 128u);
        bool v1 = hasE1 & ((unsigned)gx1 < 128u) & ((unsigned)gy1 < 128u);
        int zbase = z0 - 2;
        size_t zb = (size_t)zbase * (128 * 128);
        const float* pg0 = gt + (v0 ? (gy0 * 128 + gx0) : 0) + zb;
        const float* pp0 = pr + (v0 ? (gy0 * 128 + gx0) : 0) + zb;
        const float* pg1 = gt + (v1 ? (gy1 * 128 + gx1) : 0) + zb;
        const float* pp1 = pr + (v1 ? (gy1 * 128 + gx1) : 0) + zb;

        bool hasF1 = (tid < XS_ELEMS - 256);  // tid < 128

        // prologue: slice 0
        {
            bool zv = (unsigned)(zbase) < 128u;
            float a = 0.f, b = 0.f, c = 0.f, d = 0.f;
            if (v0 & zv) { a = pg0[0]; b = pp0[0]; }
            if (v1 & zv) { c = pg1[0]; d = pp1[0]; }
            raw[0][e0] = make_float2(a, b);
            if (hasE1) raw[0][e1] = make_float2(c, d);
        }
        __syncthreads();

        float2 bgp[5], cgp[5];
        #pragma unroll
        for (int k = 0; k < 5; k++) { bgp[k] = make_float2(0.f, 0.f); cgp[k] = make_float2(0.f, 0.f); }
        float accC = 0.f, accG = 0.f, accP = 0.f;

        #pragma unroll
        for (int zi = 0; zi < NSLICE; zi++) {
            const int cur = zi & 1, nxt = cur ^ 1;

            // prefetch slice zi+1 into registers (overlaps x-pass)
            float ng0 = 0.f, np0 = 0.f, ng1 = 0.f, np1 = 0.f;
            if (zi + 1 < NSLICE) {
                bool zv = (unsigned)(zbase + zi + 1) < 128u;
                const int zo = (zi + 1) * (128 * 128);
                if (v0 & zv) { ng0 = pg0[zo]; np0 = pp0[zo]; }
                if (v1 & zv) { ng1 = pg1[zo]; np1 = pp1[zo]; }
            }

            // x-pass: 5-wide from raw[cur] into xs[cur]; capture center
            {
                const float2* r = &raw[cur][ly * HX + lx];
                float2 s;
                s.x = r[0].x + r[1].x + r[2].x + r[3].x + r[4].x;
                s.y = r[0].y + r[1].y + r[2].y + r[3].y + r[4].y;
                xs[cur][tid] = s;
                if (hasF1) {
                    const float2* r2 = &raw[cur][(8 + ly) * HX + lx];
                    float2 s2;
                    s2.x = r2[0].x + r2[1].x + r2[2].x + r2[3].x + r2[4].x;
                    s2.y = r2[0].y + r2[1].y + r2[2].y + r2[3].y + r2[4].y;
                    xs[cur][tid + 256] = s2;
                }
                cgp[zi % 5] = raw[cur][(ly + 2) * HX + lx + 2];
            }

            // stage prefetched slice into raw[nxt]
            raw[nxt][e0] = make_float2(ng0, np0);
            if (hasE1) raw[nxt][e1] = make_float2(ng1, np1);
            __syncthreads();

            // y-pass from xs[cur]; z-pass in register ring
            {
                const float2* q = &xs[cur][ly * TX + lx];
                float2 w;
                w.x = q[0].x + q[TX].x + q[2 * TX].x + q[3 * TX].x + q[4 * TX].x;
                w.y = q[0].y + q[TX].y + q[2 * TX].y + q[3 * TX].y + q[4 * TX].y;
                bgp[zi % 5] = w;
            }

            if (zi >= 4) {
                float sg = bgp[0].x + bgp[1].x + bgp[2].x + bgp[3].x + bgp[4].x;
                float sp = bgp[0].y + bgp[1].y + bgp[2].y + bgp[3].y + bgp[4].y;
                float2 c = cgp[(zi - 2) % 5];
                float dgv = c.x - sg * (1.f / 125.f);
                float dpv = c.y - sp * (1.f / 125.f);
                accG += dgv * dgv;
                accP += dpv * dpv;
                accC += dgv * dpv;
            }
        }

        float* scr = (float*)&xs[0][0];
        float c = warp_sum(accC);
        float gg = warp_sum(accG);
        float pp = warp_sum(accP);
        int wid = tid >> 5, lane = tid & 31;
        __syncthreads();
        if (lane == 0) { scr[wid] = c; scr[8 + wid] = gg; scr[16 + wid] = pp; }
        __syncthreads();
        if (tid == 0) {
            float C = 0, G = 0, P = 0;
            #pragma unroll
            for (int w = 0; w < 8; w++) { C += scr[w]; G += scr[8 + w]; P += scr[16 + w]; }
            int base = 1 + pair * 3;
            atomicAdd(&g_acc[base + 0], (double)C);
            atomicAdd(&g_acc[base + 1], (double)G);
            atomicAdd(&g_acc[base + 2], (double)P);
        }
    } else if (blkid < LCC_BLOCKS + REG_BLOCKS) {
        // ================= reg_field: sum((a-b)^2) =================
        const float4* a = (const float4*)F0;
        const float4* b = (const float4*)F0g;
        const int n4 = (2 * 3 * VOL) / 4;
        int bid = blkid - LCC_BLOCKS;
        float acc = 0.f;
        for (int i = bid * 256 + tid; i < n4; i += REG_BLOCKS * 256) {
            float4 x = a[i], y = b[i];
            float d0 = x.x - y.x, d1 = x.y - y.y, d2 = x.z - y.z, d3 = x.w - y.w;
            acc += d0 * d0 + d1 * d1 + d2 * d2 + d3 * d3;
        }
        float* scr = (float*)&xs[0][0];
        float w = warp_sum(acc);
        if ((tid & 31) == 0) scr[tid >> 5] = w;
        __syncthreads();
        if (tid == 0) {
            float v = 0.f;
            #pragma unroll
            for (int k = 0; k < 8; k++) v += scr[k];
            atomicAdd(&g_acc[0], (double)v);
        }
    } else {
        // ================= tversky: both pairs =================
        const float4* g0 = (const float4*)S0;
        const float4* p0 = (const float4*)S0g;
        const float4* g1 = (const float4*)S1;
        const float4* p1 = (const float4*)S1g;
        const int n4 = (2 * VOL) / 4;
        int bid = blkid - LCC_BLOCKS - REG_BLOCKS;
        float pr0 = 0.f, sm0 = 0.f, pr1 = 0.f, sm1 = 0.f;
        for (int i = bid * 256 + tid; i < n4; i += TV_BLOCKS * 256) {
            float4 a = g0[i], b = p0[i];
            pr0 += a.x * b.x + a.y * b.y + a.z * b.z + a.w * b.w;
            sm0 += a.x + b.x + a.y + b.y + a.z + b.z + a.w + b.w;
            float4 cc = g1[i], dd = p1[i];
            pr1 += cc.x * dd.x + cc.y * dd.y + cc.z * dd.z + cc.w * dd.w;
            sm1 += cc.x + dd.x + cc.y + dd.y + cc.z + dd.z + cc.w + dd.w;
        }
        float* scr = (float*)&xs[0][0];
        float v0 = warp_sum(pr0), v1 = warp_sum(sm0), v2 = warp_sum(pr1), v3 = warp_sum(sm1);
        int wid = tid >> 5;
        if ((tid & 31) == 0) { scr[wid] = v0; scr[8 + wid] = v1; scr[16 + wid] = v2; scr[24 + wid] = v3; }
        __syncthreads();
        if (tid == 0) {
            float t0 = 0, t1 = 0, t2 = 0, t3 = 0;
            #pragma unroll
            for (int k = 0; k < 8; k++) { t0 += scr[k]; t1 += scr[8 + k]; t2 += scr[16 + k]; t3 += scr[24 + k]; }
            atomicAdd(&g_acc[7], (double)t0);
            atomicAdd(&g_acc[8], (double)t1);
            atomicAdd(&g_acc[9], (double)t2);
            atomicAdd(&g_acc[10], (double)t3);
        }
    }

    // ---- last-block-done finalize (thread 0 of each block takes a ticket) ----
    if (tid == 0) {
        __threadfence();
        unsigned t = atomicAdd(&g_ticket, 1u);
        if (t == TOTAL_BLOCKS - 1) {
            __threadfence();
            volatile double* acc = g_acc;

            const double omega_f = 2.0 * 3.0 * VOL;  // 12582912
            const double omega_i = 2.0 * 1.0 * VOL;  // 4194304

            double rf = sqrt(acc[0]) / omega_f;

            double num0 = acc[1] * acc[1];
            double den0 = acc[2] * acc[3];
            den0 = den0 > 1e-5 ? den0 : 1e-5;
            double lcc0 = -(num0 / den0) / omega_i;

            double num1 = acc[4] * acc[4];
            double den1 = acc[5] * acc[6];
            den1 = den1 > 1e-5 ? den1 : 1e-5;
            double lcc1 = -(num1 / den1) / omega_i;

            double s0 = acc[8] > 1e-5 ? acc[8] : 1e-5;
            double s1 = acc[10] > 1e-5 ? acc[10] : 1e-5;
            double tv0 = -acc[7] / s0;   // -0.5 * 2*prod / sum
            double tv1 = -acc[9] / s1;

            out[0] = (float)(rf + 10.0 * (lcc0 + lcc1) + 10.0 * (tv0 + tv1));

            // reset state for the next replay
            #pragma unroll
            for (int k = 0; k < 12; k++) g_acc[k] = 0.0;
            __threadfence();
            g_ticket = 0u;
        }
    }
}

extern "C" void kernel_launch(void* const* d_in, const int* in_sizes, int n_in,
                              void* d_out, int out_size) {
    const float* F0  = (const float*)d_in[0];
    const float* F0g = (const float*)d_in[1];
    const float* I0  = (const float*)d_in[2];
    const float* I0R = (const float*)d_in[3];
    const float* I1  = (const float*)d_in[4];
    const float* I1R = (const float*)d_in[5];
    const float* S0  = (const float*)d_in[6];
    const float* S0g = (const float*)d_in[7];
    const float* S1  = (const float*)d_in[8];
    const float* S1g = (const float*)d_in[9];
    float* out = (float*)d_out;

    fused_kernel<<<TOTAL_BLOCKS, 256>>>(F0, F0g, I0, I0R, I1, I1R,
                                        S0, S0g, S1, S1g, out);
}

// round 7
// speedup vs baseline: 1.2553x; 1.1549x over previous
#include <cuda_runtime.h>
#include <math.h>

#define VOL (128*128*128)

// Accumulators (double): 0 reg_sumsq | 1-3 pair0 cross/gg/pp | 4-6 pair1 | 7-8 tv0 prod/sum | 9-10 tv1
// Zero at load; last-finishing block emits result and re-zeroes for next replay.
__device__ double g_acc[12];
__device__ unsigned g_ticket;

__device__ __forceinline__ float warp_sum(float v) {
    #pragma unroll
    for (int o = 16; o > 0; o >>= 1) v += __shfl_xor_sync(0xffffffffu, v, o);
    return v;
}

// ---------------------------------------------------------------------------
// LCC geometry: tile 64(x) x 8(y) x 32(z), halo 2. Each thread owns 2
// consecutive x outputs (float2 granularity). One barrier per z-slice.
// ---------------------------------------------------------------------------
#define TXO 64            // x outputs per tile
#define TY 8
#define TZ 32
#define HXF 68            // raw row width in floats
#define HX2 34            // raw row width in float2
#define HY 12
#define NSLICE (TZ + 4)   // 36
#define RAW_F (HY * HXF)  // 816 floats
#define RAW_F2 (HY * HX2) // 408 float2 elements
#define XS_F (HY * TXO)   // 768 floats

#define LCC_BLOCKS 512
#define REG_BLOCKS 512
#define TV_BLOCKS  256
#define TOTAL_BLOCKS (LCC_BLOCKS + REG_BLOCKS + TV_BLOCKS)

__global__ __launch_bounds__(256, 4) void fused_kernel(
    const float* __restrict__ F0, const float* __restrict__ F0g,
    const float* __restrict__ I0, const float* __restrict__ I0R,
    const float* __restrict__ I1, const float* __restrict__ I1R,
    const float* __restrict__ S0, const float* __restrict__ S0g,
    const float* __restrict__ S1, const float* __restrict__ S1g,
    float* __restrict__ out) {

    __shared__ float rawG[2][RAW_F], rawP[2][RAW_F];
    __shared__ float xsG[2][XS_F], xsP[2][XS_F];

    int blkid = blockIdx.x;
    int tid = threadIdx.x;

    if (blkid < LCC_BLOCKS) {
        // ================= LCC =================
        int blk = blkid;
        int x2_0 = (blk & 1) * 32;            // tile x origin in float2 units
        int y0 = ((blk >> 1) & 15) * TY;
        int z0 = ((blk >> 5) & 3) * TZ;
        int batch = (blk >> 7) & 1;
        int pair = blk >> 8;

        const float2* gt = (const float2*)((pair == 0 ? I0 : I1) + (size_t)batch * VOL);
        const float2* pr = (const float2*)((pair == 0 ? I0R : I1R) + (size_t)batch * VOL);

        int lx = tid & 31, ly = tid >> 5;

        // ---- load roles (float2 elements, 408 per slice per array)
        int e0 = tid, e1 = tid + 256;
        int r0 = e0 / HX2, c0 = e0 - r0 * HX2;
        int r1 = e1 / HX2, c1 = e1 - r1 * HX2;
        int gxa = x2_0 - 1 + c0, gya = y0 + r0 - 2;
        int gxb = x2_0 - 1 + c1, gyb = y0 + r1 - 2;
        bool hasE1 = (e1 < RAW_F2);           // tid < 152
        bool va = ((unsigned)gxa < 64u) & ((unsigned)gya < 128u);
        bool vb = hasE1 & ((unsigned)gxb < 64u) & ((unsigned)gyb < 128u);
        int zbase = z0 - 2;
        long zb = (long)zbase * 8192;         // slice stride in float2
        const float2* pga = gt + (va ? (gya * 64 + gxa) : 0) + zb;
        const float2* ppa = pr + (va ? (gya * 64 + gxa) : 0) + zb;
        const float2* pgb = gt + (vb ? (gyb * 64 + gxb) : 0) + zb;
        const float2* ppb = pr + (vb ? (gyb * 64 + gxb) : 0) + zb;
        int s0 = r0 * HXF + 2 * c0;
        int s1 = r1 * HXF + 2 * c1;

        // prologue: slice 0 into buffer 0
        {
            bool zv = (unsigned)zbase < 128u;
            float2 ga = make_float2(0.f, 0.f), pa = ga, gb = ga, pb = ga;
            if (va & zv) { ga = pga[0]; pa = ppa[0]; }
            if (vb & zv) { gb = pgb[0]; pb = ppb[0]; }
            *(float2*)&rawG[0][s0] = ga;
            *(float2*)&rawP[0][s0] = pa;
            if (hasE1) { *(float2*)&rawG[0][s1] = gb; *(float2*)&rawP[0][s1] = pb; }
        }
        __syncthreads();

        float2 bg[5], bp[5], cg3[3], cp3[3];
        #pragma unroll
        for (int k = 0; k < 5; k++) { bg[k] = make_float2(0.f, 0.f); bp[k] = make_float2(0.f, 0.f); }
        #pragma unroll
        for (int k = 0; k < 3; k++) { cg3[k] = make_float2(0.f, 0.f); cp3[k] = make_float2(0.f, 0.f); }
        float accC = 0.f, accG = 0.f, accP = 0.f;

        #pragma unroll
        for (int zi = 0; zi < NSLICE; zi++) {
            const int cur = zi & 1, nxt = cur ^ 1;

            // prefetch slice zi+1 (overlaps x-pass)
            float2 nga = make_float2(0.f, 0.f), npa = nga, ngb = nga, npb = nga;
            if (zi + 1 < NSLICE) {
                bool zv = (unsigned)(zbase + zi + 1) < 128u;
                const int zo = (zi + 1) * 8192;
                if (va & zv) { nga = pga[zo]; npa = ppa[zo]; }
                if (vb & zv) { ngb = pgb[zo]; npb = ppb[zo]; }
            }

            // x-pass: raw floats [2lx .. 2lx+5] -> sums for outputs 2lx, 2lx+1
            {
                const float* rg = &rawG[cur][ly * HXF + 2 * lx];
                float2 a = *(const float2*)rg, b = *(const float2*)(rg + 2), c = *(const float2*)(rg + 4);
                float tg = a.y + b.x + b.y + c.x;
                *(float2*)&xsG[cur][ly * TXO + 2 * lx] = make_float2(a.x + tg, tg + c.y);
                const float* rp = &rawP[cur][ly * HXF + 2 * lx];
                float2 d = *(const float2*)rp, e = *(const float2*)(rp + 2), f = *(const float2*)(rp + 4);
                float tp = d.y + e.x + e.y + f.x;
                *(float2*)&xsP[cur][ly * TXO + 2 * lx] = make_float2(d.x + tp, tp + f.y);
                if (tid < 128) {
                    const int r8 = (8 + ly) * HXF + 2 * lx;
                    const float* rg2 = &rawG[cur][r8];
                    float2 a2 = *(const float2*)rg2, b2 = *(const float2*)(rg2 + 2), c2 = *(const float2*)(rg2 + 4);
                    float tg2 = a2.y + b2.x + b2.y + c2.x;
                    *(float2*)&xsG[cur][(8 + ly) * TXO + 2 * lx] = make_float2(a2.x + tg2, tg2 + c2.y);
                    const float* rp2 = &rawP[cur][r8];
                    float2 d2 = *(const float2*)rp2, e2 = *(const float2*)(rp2 + 2), f2 = *(const float2*)(rp2 + 4);
                    float tp2 = d2.y + e2.x + e2.y + f2.x;
                    *(float2*)&xsP[cur][(8 + ly) * TXO + 2 * lx] = make_float2(d2.x + tp2, tp2 + f2.y);
                }
                // center values for this slice (row ly+2, floats 2lx+2, 2lx+3)
                cg3[zi % 3] = *(const float2*)&rawG[cur][(ly + 2) * HXF + 2 * lx + 2];
                cp3[zi % 3] = *(const float2*)&rawP[cur][(ly + 2) * HXF + 2 * lx + 2];
            }

            // stage prefetched slice into raw[nxt]
            *(float2*)&rawG[nxt][s0] = nga;
            *(float2*)&rawP[nxt][s0] = npa;
            if (hasE1) { *(float2*)&rawG[nxt][s1] = ngb; *(float2*)&rawP[nxt][s1] = npb; }
            __syncthreads();

            // y-pass: 5-row window from xs; z held in register ring
            {
                const float* qg = &xsG[cur][ly * TXO + 2 * lx];
                float2 w0 = *(const float2*)qg;
                float2 w1 = *(const float2*)(qg + TXO);
                float2 w2 = *(const float2*)(qg + 2 * TXO);
                float2 w3 = *(const float2*)(qg + 3 * TXO);
                float2 w4 = *(const float2*)(qg + 4 * TXO);
                bg[zi % 5] = make_float2(w0.x + w1.x + w2.x + w3.x + w4.x,
                                         w0.y + w1.y + w2.y + w3.y + w4.y);
                const float* qp = &xsP[cur][ly * TXO + 2 * lx];
                float2 u0 = *(const float2*)qp;
                float2 u1 = *(const float2*)(qp + TXO);
                float2 u2 = *(const float2*)(qp + 2 * TXO);
                float2 u3 = *(const float2*)(qp + 3 * TXO);
                float2 u4 = *(const float2*)(qp + 4 * TXO);
                bp[zi % 5] = make_float2(u0.x + u1.x + u2.x + u3.x + u4.x,
                                         u0.y + u1.y + u2.y + u3.y + u4.y);
            }

            if (zi >= 4) {
                float sg0 = bg[0].x + bg[1].x + bg[2].x + bg[3].x + bg[4].x;
                float sg1 = bg[0].y + bg[1].y + bg[2].y + bg[3].y + bg[4].y;
                float sp0 = bp[0].x + bp[1].x + bp[2].x + bp[3].x + bp[4].x;
                float sp1 = bp[0].y + bp[1].y + bp[2].y + bp[3].y + bp[4].y;
                float2 cg = cg3[(zi - 2) % 3], cp = cp3[(zi - 2) % 3];
                float d0g = cg.x - sg0 * (1.f / 125.f);
                float d1g = cg.y - sg1 * (1.f / 125.f);
                float d0p = cp.x - sp0 * (1.f / 125.f);
                float d1p = cp.y - sp1 * (1.f / 125.f);
                accG += d0g * d0g + d1g * d1g;
                accP += d0p * d0p + d1p * d1p;
                accC += d0g * d0p + d1g * d1p;
            }
        }

        float* scr = &xsG[0][0];
        float c = warp_sum(accC);
        float gg = warp_sum(accG);
        float pp = warp_sum(accP);
        int wid = tid >> 5, lane = tid & 31;
        __syncthreads();
        if (lane == 0) { scr[wid] = c; scr[8 + wid] = gg; scr[16 + wid] = pp; }
        __syncthreads();
        if (tid == 0) {
            float C = 0, G = 0, P = 0;
            #pragma unroll
            for (int w = 0; w < 8; w++) { C += scr[w]; G += scr[8 + w]; P += scr[16 + w]; }
            int base = 1 + pair * 3;
            atomicAdd(&g_acc[base + 0], (double)C);
            atomicAdd(&g_acc[base + 1], (double)G);
            atomicAdd(&g_acc[base + 2], (double)P);
        }
    } else if (blkid < LCC_BLOCKS + REG_BLOCKS) {
        // ================= reg_field: sum((a-b)^2) =================
        const float4* a = (const float4*)F0;
        const float4* b = (const float4*)F0g;
        const int n4 = (2 * 3 * VOL) / 4;
        int bid = blkid - LCC_BLOCKS;
        float acc = 0.f;
        for (int i = bid * 256 + tid; i < n4; i += REG_BLOCKS * 256) {
            float4 x = a[i], y = b[i];
            float d0 = x.x - y.x, d1 = x.y - y.y, d2 = x.z - y.z, d3 = x.w - y.w;
            acc += d0 * d0 + d1 * d1 + d2 * d2 + d3 * d3;
        }
        float* scr = &xsG[0][0];
        float w = warp_sum(acc);
        if ((tid & 31) == 0) scr[tid >> 5] = w;
        __syncthreads();
        if (tid == 0) {
            float v = 0.f;
            #pragma unroll
            for (int k = 0; k < 8; k++) v += scr[k];
            atomicAdd(&g_acc[0], (double)v);
        }
    } else {
        // ================= tversky: both pairs =================
        const float4* g0 = (const float4*)S0;
        const float4* p0 = (const float4*)S0g;
        const float4* g1 = (const float4*)S1;
        const float4* p1 = (const float4*)S1g;
        const int n4 = (2 * VOL) / 4;
        int bid = blkid - LCC_BLOCKS - REG_BLOCKS;
        float pr0 = 0.f, sm0 = 0.f, pr1 = 0.f, sm1 = 0.f;
        for (int i = bid * 256 + tid; i < n4; i += TV_BLOCKS * 256) {
            float4 a = g0[i], b = p0[i];
            pr0 += a.x * b.x + a.y * b.y + a.z * b.z + a.w * b.w;
            sm0 += a.x + b.x + a.y + b.y + a.z + b.z + a.w + b.w;
            float4 cc = g1[i], dd = p1[i];
            pr1 += cc.x * dd.x + cc.y * dd.y + cc.z * dd.z + cc.w * dd.w;
            sm1 += cc.x + dd.x + cc.y + dd.y + cc.z + dd.z + cc.w + dd.w;
        }
        float* scr = &xsG[0][0];
        float v0 = warp_sum(pr0), v1 = warp_sum(sm0), v2 = warp_sum(pr1), v3 = warp_sum(sm1);
        int wid = tid >> 5;
        if ((tid & 31) == 0) { scr[wid] = v0; scr[8 + wid] = v1; scr[16 + wid] = v2; scr[24 + wid] = v3; }
        __syncthreads();
        if (tid == 0) {
            float t0 = 0, t1 = 0, t2 = 0, t3 = 0;
            #pragma unroll
            for (int k = 0; k < 8; k++) { t0 += scr[k]; t1 += scr[8 + k]; t2 += scr[16 + k]; t3 += scr[24 + k]; }
            atomicAdd(&g_acc[7], (double)t0);
            atomicAdd(&g_acc[8], (double)t1);
            atomicAdd(&g_acc[9], (double)t2);
            atomicAdd(&g_acc[10], (double)t3);
        }
    }

    // ---- last-block-done finalize ----
    if (tid == 0) {
        __threadfence();
        unsigned t = atomicAdd(&g_ticket, 1u);
        if (t == TOTAL_BLOCKS - 1) {
            __threadfence();
            volatile double* acc = g_acc;

            const double omega_f = 2.0 * 3.0 * VOL;
            const double omega_i = 2.0 * 1.0 * VOL;

            double rf = sqrt(acc[0]) / omega_f;

            double num0 = acc[1] * acc[1];
            double den0 = acc[2] * acc[3];
            den0 = den0 > 1e-5 ? den0 : 1e-5;
            double lcc0 = -(num0 / den0) / omega_i;

            double num1 = acc[4] * acc[4];
            double den1 = acc[5] * acc[6];
            den1 = den1 > 1e-5 ? den1 : 1e-5;
            double lcc1 = -(num1 / den1) / omega_i;

            double s0 = acc[8] > 1e-5 ? acc[8] : 1e-5;
            double s1 = acc[10] > 1e-5 ? acc[10] : 1e-5;
            double tv0 = -acc[7] / s0;
            double tv1 = -acc[9] / s1;

            out[0] = (float)(rf + 10.0 * (lcc0 + lcc1) + 10.0 * (tv0 + tv1));

            #pragma unroll
            for (int k = 0; k < 12; k++) g_acc[k] = 0.0;
            __threadfence();
            g_ticket = 0u;
        }
    }
}

extern "C" void kernel_launch(void* const* d_in, const int* in_sizes, int n_in,
                              void* d_out, int out_size) {
    const float* F0  = (const float*)d_in[0];
    const float* F0g = (const float*)d_in[1];
    const float* I0  = (const float*)d_in[2];
    const float* I0R = (const float*)d_in[3];
    const float* I1  = (const float*)d_in[4];
    const float* I1R = (const float*)d_in[5];
    const float* S0  = (const float*)d_in[6];
    const float* S0g = (const float*)d_in[7];
    const float* S1  = (const float*)d_in[8];
    const float* S1g = (const float*)d_in[9];
    float* out = (float*)d_out;

    fused_kernel<<<TOTAL_BLOCKS, 256>>>(F0, F0g, I0, I0R, I1, I1R,
                                        S0, S0g, S1, S1g, out);
}